// round 14
// baseline (speedup 1.0000x reference)
#include <cuda_runtime.h>
#include <cuda_fp16.h>
#include <stdint.h>

#define BATCH 16
#define NQ 2048
#define MK 2048
#define DH 128
#define DV 128
#define BM 64
#define BN 64
#define NTC 128
#define SCALE_LOG2E 0.1275174556684344f   // (1/sqrt(128)) * log2(e)

// fp16 pre-converted operands, [b][m][d]. Q pre-scaled by SCALE_LOG2E.
// K rows with m >= keylen[b] are zeroed (exactly reproduces reference masking).
__device__ __half g_Qh[(size_t)BATCH * NQ * DH];
__device__ __half g_Kh[(size_t)BATCH * MK * DH];
__device__ __half g_Vh[(size_t)BATCH * MK * DV];

// smem: Q 16KB + K ring3 48KB + V ring3 48KB = 112KB/CTA (2 CTAs/SM)
#define SM_Q 0
#define SM_K(i) (16384 + (i) * 16384)
#define SM_V(i) (65536 + (i) * 16384)
#define SM_TOTAL 114688

__device__ __forceinline__ int swz(int row, int d) {      // rows of 128 fp16
    return row * 128 + ((((d >> 3) ^ (row & 7)) << 3) | (d & 7));
}
__device__ __forceinline__ uint32_t sptr(const void* p) {
    return (uint32_t)__cvta_generic_to_shared(p);
}
__device__ __forceinline__ void cp16(uint32_t d, const void* s) {
    asm volatile("cp.async.cg.shared.global [%0], [%1], 16;" :: "r"(d), "l"(s));
}
__device__ __forceinline__ void cpc()  { asm volatile("cp.async.commit_group;"); }
__device__ __forceinline__ void cpw0() { asm volatile("cp.async.wait_group 0;"); }
__device__ __forceinline__ void cpw1() { asm volatile("cp.async.wait_group 1;"); }

__device__ __forceinline__ void ldsm_x4(uint32_t a, uint32_t& r0, uint32_t& r1,
                                        uint32_t& r2, uint32_t& r3) {
    asm volatile("ldmatrix.sync.aligned.m8n8.x4.shared.b16 {%0,%1,%2,%3}, [%4];"
                 : "=r"(r0), "=r"(r1), "=r"(r2), "=r"(r3) : "r"(a));
}
__device__ __forceinline__ void ldsm_x4_t(uint32_t a, uint32_t& r0, uint32_t& r1,
                                          uint32_t& r2, uint32_t& r3) {
    asm volatile("ldmatrix.sync.aligned.m8n8.x4.trans.shared.b16 {%0,%1,%2,%3}, [%4];"
                 : "=r"(r0), "=r"(r1), "=r"(r2), "=r"(r3) : "r"(a));
}
__device__ __forceinline__ void mma_f16(float* c, const uint32_t* a,
                                        uint32_t b0, uint32_t b1) {
    asm volatile(
        "mma.sync.aligned.m16n8k16.row.col.f32.f16.f16.f32 "
        "{%0,%1,%2,%3}, {%4,%5,%6,%7}, {%8,%9}, {%0,%1,%2,%3};"
        : "+f"(c[0]), "+f"(c[1]), "+f"(c[2]), "+f"(c[3])
        : "r"(a[0]), "r"(a[1]), "r"(a[2]), "r"(a[3]), "r"(b0), "r"(b1));
}
__device__ __forceinline__ uint32_t packh2(float x, float y) {
    __half2 h = __floats2half2_rn(x, y);
    return *reinterpret_cast<uint32_t*>(&h);
}

__device__ __forceinline__ void stage64(uint32_t S, int off, const __half* src, int tid) {
    #pragma unroll
    for (int i = 0; i < 8; ++i) {
        int c = tid + i * NTC;             // 0..1023
        int row = c >> 4, ch = c & 15;
        cp16(S + off + 2 * (row * 128 + ((ch ^ (row & 7)) << 3)),
             src + (size_t)row * 128 + ch * 8);
    }
}

__device__ __forceinline__ void qk_block(float (&sacc)[8][4], uint32_t kbuf,
                                         const uint32_t (&qf)[8][4], int lane) {
    #pragma unroll
    for (int nt = 0; nt < 8; ++nt) {
        sacc[nt][0] = 0.f; sacc[nt][1] = 0.f; sacc[nt][2] = 0.f; sacc[nt][3] = 0.f;
    }
    const int key = lane & 7;
    const int dbase = (lane >> 3) << 3;
    #pragma unroll
    for (int nt = 0; nt < 8; ++nt) {
        int krow = nt * 8 + key;
        #pragma unroll
        for (int kc2 = 0; kc2 < 4; ++kc2) {
            int d = kc2 * 32 + dbase;
            uint32_t k0, k1, k2, k3;
            ldsm_x4(kbuf + 2 * swz(krow, d), k0, k1, k2, k3);
            mma_f16(sacc[nt], qf[2 * kc2],     k0, k1);
            mma_f16(sacc[nt], qf[2 * kc2 + 1], k2, k3);
        }
    }
}

// Scores already log2-domain (scale folded into Q); K pad pre-zeroed,
// so masking is needed only on the diagonal block.
__device__ __forceinline__ void soft_block(float (&sacc)[8][4], int kb, int tile,
                                           int rA, int rB, int lane,
                                           float& lA, float& lB) {
    float sA = 0.f, sB = 0.f;
    if (kb == tile) {
        const int kbBase = kb * BN;
        #pragma unroll
        for (int nt = 0; nt < 8; ++nt) {
            int colbase = kbBase + nt * 8 + 2 * (lane & 3);
            #pragma unroll
            for (int e = 0; e < 2; ++e) {
                int col = colbase + e;
                float p0 = exp2f((col > rA) ? -1e30f : sacc[nt][e]);
                sacc[nt][e] = p0;  sA += p0;
                float p1 = exp2f((col > rB) ? -1e30f : sacc[nt][e + 2]);
                sacc[nt][e + 2] = p1;  sB += p1;
            }
        }
    } else {
        #pragma unroll
        for (int nt = 0; nt < 8; ++nt) {
            #pragma unroll
            for (int e = 0; e < 2; ++e) {
                float p0 = exp2f(sacc[nt][e]);
                sacc[nt][e] = p0;  sA += p0;
                float p1 = exp2f(sacc[nt][e + 2]);
                sacc[nt][e + 2] = p1;  sB += p1;
            }
        }
    }
    lA += sA;  lB += sB;
}

__device__ __forceinline__ void pv_block(float (&oacc)[16][4],
                                         const float (&sacc)[8][4],
                                         uint32_t vbuf, int lane) {
    const int vkey = lane & 15;
    const int nsel = (lane >> 4) << 3;
    #pragma unroll
    for (int kt = 0; kt < 4; ++kt) {
        uint32_t pa[4];
        pa[0] = packh2(sacc[2 * kt][0],     sacc[2 * kt][1]);
        pa[1] = packh2(sacc[2 * kt][2],     sacc[2 * kt][3]);
        pa[2] = packh2(sacc[2 * kt + 1][0], sacc[2 * kt + 1][1]);
        pa[3] = packh2(sacc[2 * kt + 1][2], sacc[2 * kt + 1][3]);
        int krow = kt * 16 + vkey;
        #pragma unroll
        for (int nt2 = 0; nt2 < 8; ++nt2) {
            int n0 = nt2 * 16 + nsel;
            uint32_t v0, v1, v2, v3;
            ldsm_x4_t(vbuf + 2 * swz(krow, n0), v0, v1, v2, v3);
            mma_f16(oacc[2 * nt2],     pa, v0, v1);
            mma_f16(oacc[2 * nt2 + 1], pa, v2, v3);
        }
    }
}

// ---- pre-pass: Q scaled, K pad-zeroed, V plain ----
__global__ void cvt_kernel(const float* __restrict__ q, const float* __restrict__ k,
                           const float* __restrict__ v, const int* __restrict__ pad)
{
    const size_t T = (size_t)BATCH * 2048 * 128 / 4;
    for (size_t i = (size_t)blockIdx.x * blockDim.x + threadIdx.x;
         i < 3 * T; i += (size_t)gridDim.x * blockDim.x) {
        if (i < T) {
            float4 x = reinterpret_cast<const float4*>(q)[i];
            uint2 h;
            h.x = packh2(x.x * SCALE_LOG2E, x.y * SCALE_LOG2E);
            h.y = packh2(x.z * SCALE_LOG2E, x.w * SCALE_LOG2E);
            *reinterpret_cast<uint2*>(g_Qh + i * 4) = h;
        } else if (i < 2 * T) {
            size_t f = i - T;
            size_t row = f >> 5;
            int b = (int)(row >> 11), m = (int)(row & 2047);
            uint2 h;
            if (m >= MK - pad[b]) {
                h.x = 0u; h.y = 0u;
            } else {
                float4 x = reinterpret_cast<const float4*>(k)[f];
                h.x = packh2(x.x, x.y);
                h.y = packh2(x.z, x.w);
            }
            *reinterpret_cast<uint2*>(g_Kh + f * 4) = h;
        } else {
            size_t f = i - 2 * T;
            float4 x = reinterpret_cast<const float4*>(v)[f];
            uint2 h;
            h.x = packh2(x.x, x.y);
            h.y = packh2(x.z, x.w);
            *reinterpret_cast<uint2*>(g_Vh + f * 4) = h;
        }
    }
}

// ---- main kernel: BM=64, 4 warps, 2 CTAs/SM, depth-2 pipelined loop ----
__global__ __launch_bounds__(NTC, 2)
void fa_f16e_kernel(const int* __restrict__ pad, float* __restrict__ out)
{
    extern __shared__ __half sm[];
    const uint32_t S = sptr(sm);
    const int tid = threadIdx.x, lane = tid & 31, warp = tid >> 5;
    const int b = blockIdx.x & 15, tile = (NQ / BM - 1) - (blockIdx.x >> 4);
    const int nkb = tile + 1;

    const __half* qsrc  = g_Qh + ((size_t)b * NQ + (size_t)tile * BM) * DH;
    const __half* kbase = g_Kh + (size_t)b * MK * DH;
    const __half* vbase = g_Vh + (size_t)b * MK * DV;

    // prologue: group0 = Q + K0 + V0; group1 = K1 + V1
    stage64(S, SM_Q, qsrc, tid);
    stage64(S, SM_K(0), kbase, tid);
    stage64(S, SM_V(0), vbase, tid);
    cpc();
    if (nkb > 1) {
        stage64(S, SM_K(1), kbase + (size_t)BN * DH, tid);
        stage64(S, SM_V(1), vbase + (size_t)BN * DV, tid);
        cpc();
        cpw1();                 // Q + K0/V0 resident (K1/V1 may fly)
    } else {
        cpw0();
    }
    __syncthreads();

    // persistent Q fragments (warp rows 16w..16w+16)
    const int r0w = warp * 16;
    uint32_t qf[8][4];
    {
        int qrow = r0w + (lane & 15);
        int dsel = (lane >> 4) << 3;
        #pragma unroll
        for (int kc = 0; kc < 8; ++kc)
            ldsm_x4(S + SM_Q + 2 * swz(qrow, kc * 16 + dsel),
                    qf[kc][0], qf[kc][1], qf[kc][2], qf[kc][3]);
    }

    const int rA = tile * BM + r0w + (lane >> 2);
    const int rB = rA + 8;
    float lA = 0.f, lB = 0.f;
    float oacc[16][4];
    #pragma unroll
    for (int t = 0; t < 16; ++t) {
        oacc[t][0] = 0.f; oacc[t][1] = 0.f; oacc[t][2] = 0.f; oacc[t][3] = 0.f;
    }

    float saccA[8][4], saccB[8][4];
    qk_block(saccA, S + SM_K(0), qf, lane);

    // Depth-2 pipelined loop, unrolled x2 for compile-time sacc binding.
    // Per iter: [wait kb+1; QK(kb+1); stage kb+2]  then  soft(kb); PV(kb).
    int kb = 0;
    while (true) {
        // --- even sub-iteration: process kb with saccA, fill saccB ---
        if (kb + 1 < nkb) {
            cpw0();
            __syncthreads();               // K/V[kb+1] visible; PV[kb-1] sealed
            qk_block(saccB, S + SM_K((kb + 1) % 3), qf, lane);
            if (kb + 2 < nkb) {
                stage64(S, SM_K((kb + 2) % 3), kbase + (size_t)(kb + 2) * BN * DH, tid);
                stage64(S, SM_V((kb + 2) % 3), vbase + (size_t)(kb + 2) * BN * DV, tid);
                cpc();
            }
        }
        soft_block(saccA, kb, tile, rA, rB, lane, lA, lB);
        pv_block(oacc, saccA, S + SM_V(kb % 3), lane);
        if (++kb >= nkb) break;

        // --- odd sub-iteration: process kb with saccB, fill saccA ---
        if (kb + 1 < nkb) {
            cpw0();
            __syncthreads();
            qk_block(saccA, S + SM_K((kb + 1) % 3), qf, lane);
            if (kb + 2 < nkb) {
                stage64(S, SM_K((kb + 2) % 3), kbase + (size_t)(kb + 2) * BN * DH, tid);
                stage64(S, SM_V((kb + 2) % 3), vbase + (size_t)(kb + 2) * BN * DV, tid);
                cpc();
            }
        }
        soft_block(saccB, kb, tile, rA, rB, lane, lA, lB);
        pv_block(oacc, saccB, S + SM_V(kb % 3), lane);
        if (++kb >= nkb) break;
    }

    // epilogue
    lA += __shfl_xor_sync(0xffffffffu, lA, 1);
    lA += __shfl_xor_sync(0xffffffffu, lA, 2);
    lB += __shfl_xor_sync(0xffffffffu, lB, 1);
    lB += __shfl_xor_sync(0xffffffffu, lB, 2);
    const float invA = 1.0f / lA;
    const float invB = 1.0f / lB;

    float* obase = out + (size_t)b * NQ * DV;
    #pragma unroll
    for (int t = 0; t < 16; ++t) {
        int col = t * 8 + 2 * (lane & 3);
        float2 va = make_float2(oacc[t][0] * invA, oacc[t][1] * invA);
        float2 vb = make_float2(oacc[t][2] * invB, oacc[t][3] * invB);
        *(float2*)(obase + (size_t)rA * DV + col) = va;
        *(float2*)(obase + (size_t)rB * DV + col) = vb;
    }
}

extern "C" void kernel_launch(void* const* d_in, const int* in_sizes, int n_in,
                              void* d_out, int out_size)
{
    const float* q   = (const float*)d_in[0];
    const float* k   = (const float*)d_in[1];
    const float* v   = (const float*)d_in[2];
    const int*   pad = (const int*)d_in[3];
    float* out = (float*)d_out;

    cvt_kernel<<<2048, 256>>>(q, k, v, pad);

    cudaFuncSetAttribute(fa_f16e_kernel,
                         cudaFuncAttributeMaxDynamicSharedMemorySize, SM_TOTAL);
    fa_f16e_kernel<<<(NQ / BM) * BATCH, NTC, SM_TOTAL>>>(pad, out);
}

// round 15
// speedup vs baseline: 1.0590x; 1.0590x over previous
#include <cuda_runtime.h>
#include <cuda_fp16.h>
#include <stdint.h>

#define BATCH 16
#define NQ 2048
#define MK 2048
#define DH 128
#define DV 128
#define BM 64
#define BN 64
#define NTC 128
#define SCALE_LOG2E 0.1275174556684344f   // (1/sqrt(128)) * log2(e)

// fp16 pre-converted operands, [b][m][d]. Q pre-scaled by SCALE_LOG2E.
// K rows with m >= keylen[b] are zeroed (exactly reproduces reference masking).
__device__ __half g_Qh[(size_t)BATCH * NQ * DH];
__device__ __half g_Kh[(size_t)BATCH * MK * DH];
__device__ __half g_Vh[(size_t)BATCH * MK * DV];

// smem: Q 16KB + K ring3 48KB + V ring3 48KB = 112KB/CTA (2 CTAs/SM)
#define SM_Q 0
#define SM_K(i) (16384 + (i) * 16384)
#define SM_V(i) (65536 + (i) * 16384)
#define SM_TOTAL 114688

__device__ __forceinline__ int swz(int row, int d) {      // rows of 128 fp16
    return row * 128 + ((((d >> 3) ^ (row & 7)) << 3) | (d & 7));
}
__device__ __forceinline__ uint32_t sptr(const void* p) {
    return (uint32_t)__cvta_generic_to_shared(p);
}
__device__ __forceinline__ void cp16(uint32_t d, const void* s) {
    asm volatile("cp.async.cg.shared.global [%0], [%1], 16;" :: "r"(d), "l"(s));
}
__device__ __forceinline__ void cpc()  { asm volatile("cp.async.commit_group;"); }
__device__ __forceinline__ void cpw0() { asm volatile("cp.async.wait_group 0;"); }
__device__ __forceinline__ void cpw1() { asm volatile("cp.async.wait_group 1;"); }

__device__ __forceinline__ void ldsm_x4(uint32_t a, uint32_t& r0, uint32_t& r1,
                                        uint32_t& r2, uint32_t& r3) {
    asm volatile("ldmatrix.sync.aligned.m8n8.x4.shared.b16 {%0,%1,%2,%3}, [%4];"
                 : "=r"(r0), "=r"(r1), "=r"(r2), "=r"(r3) : "r"(a));
}
__device__ __forceinline__ void ldsm_x4_t(uint32_t a, uint32_t& r0, uint32_t& r1,
                                          uint32_t& r2, uint32_t& r3) {
    asm volatile("ldmatrix.sync.aligned.m8n8.x4.trans.shared.b16 {%0,%1,%2,%3}, [%4];"
                 : "=r"(r0), "=r"(r1), "=r"(r2), "=r"(r3) : "r"(a));
}
__device__ __forceinline__ void mma_f16(float* c, const uint32_t* a,
                                        uint32_t b0, uint32_t b1) {
    asm volatile(
        "mma.sync.aligned.m16n8k16.row.col.f32.f16.f16.f32 "
        "{%0,%1,%2,%3}, {%4,%5,%6,%7}, {%8,%9}, {%0,%1,%2,%3};"
        : "+f"(c[0]), "+f"(c[1]), "+f"(c[2]), "+f"(c[3])
        : "r"(a[0]), "r"(a[1]), "r"(a[2]), "r"(a[3]), "r"(b0), "r"(b1));
}
__device__ __forceinline__ uint32_t packh2(float x, float y) {
    __half2 h = __floats2half2_rn(x, y);
    return *reinterpret_cast<uint32_t*>(&h);
}

__device__ __forceinline__ void stage64(uint32_t S, int off, const __half* src, int tid) {
    #pragma unroll
    for (int i = 0; i < 8; ++i) {
        int c = tid + i * NTC;             // 0..1023
        int row = c >> 4, ch = c & 15;
        cp16(S + off + 2 * (row * 128 + ((ch ^ (row & 7)) << 3)),
             src + (size_t)row * 128 + ch * 8);
    }
}

__device__ __forceinline__ void qk_block(float (&sacc)[8][4], uint32_t kbuf,
                                         const uint32_t (&qf)[8][4], int lane) {
    #pragma unroll
    for (int nt = 0; nt < 8; ++nt) {
        sacc[nt][0] = 0.f; sacc[nt][1] = 0.f; sacc[nt][2] = 0.f; sacc[nt][3] = 0.f;
    }
    const int key = lane & 7;
    const int dbase = (lane >> 3) << 3;
    #pragma unroll
    for (int nt = 0; nt < 8; ++nt) {
        int krow = nt * 8 + key;
        #pragma unroll
        for (int kc2 = 0; kc2 < 4; ++kc2) {
            int d = kc2 * 32 + dbase;
            uint32_t k0, k1, k2, k3;
            ldsm_x4(kbuf + 2 * swz(krow, d), k0, k1, k2, k3);
            mma_f16(sacc[nt], qf[2 * kc2],     k0, k1);
            mma_f16(sacc[nt], qf[2 * kc2 + 1], k2, k3);
        }
    }
}

// Fused softmax+PV for one kt slice (keys 16*kt .. 16*kt+15).
// soft(kt+1)'s MUFU issues while PV(kt)'s HMMAs drain in the tensor pipe.
__device__ __forceinline__ void soft_pv_kt(float (&sacc)[8][4], float (&oacc)[16][4],
                                           uint32_t vbuf, int kt, bool diag,
                                           int kbBase, int rA, int rB, int lane,
                                           float& lA, float& lB) {
    float* s0 = sacc[2 * kt];
    float* s1 = sacc[2 * kt + 1];
    float sA = 0.f, sB = 0.f;
    if (diag) {
        const int c0 = kbBase + 2 * kt * 8 + 2 * (lane & 3);
        const int c1 = c0 + 8;     // second nt of the pair
        #pragma unroll
        for (int e = 0; e < 2; ++e) {
            float p;
            p = exp2f((c0 + e > rA) ? -1e30f : s0[e]);     s0[e] = p;     sA += p;
            p = exp2f((c0 + e > rB) ? -1e30f : s0[e + 2]); s0[e + 2] = p; sB += p;
            p = exp2f((c1 + e > rA) ? -1e30f : s1[e]);     s1[e] = p;     sA += p;
            p = exp2f((c1 + e > rB) ? -1e30f : s1[e + 2]); s1[e + 2] = p; sB += p;
        }
    } else {
        #pragma unroll
        for (int e = 0; e < 2; ++e) {
            float p;
            p = exp2f(s0[e]);     s0[e] = p;     sA += p;
            p = exp2f(s0[e + 2]); s0[e + 2] = p; sB += p;
            p = exp2f(s1[e]);     s1[e] = p;     sA += p;
            p = exp2f(s1[e + 2]); s1[e + 2] = p; sB += p;
        }
    }
    lA += sA;  lB += sB;

    uint32_t pa[4];
    pa[0] = packh2(s0[0], s0[1]);
    pa[1] = packh2(s0[2], s0[3]);
    pa[2] = packh2(s1[0], s1[1]);
    pa[3] = packh2(s1[2], s1[3]);

    const int krow = kt * 16 + (lane & 15);
    const int nsel = (lane >> 4) << 3;
    #pragma unroll
    for (int nt2 = 0; nt2 < 8; ++nt2) {
        int n0 = nt2 * 16 + nsel;
        uint32_t v0, v1, v2, v3;
        ldsm_x4_t(vbuf + 2 * swz(krow, n0), v0, v1, v2, v3);
        mma_f16(oacc[2 * nt2],     pa, v0, v1);
        mma_f16(oacc[2 * nt2 + 1], pa, v2, v3);
    }
}

// ---- pre-pass: Q scaled, K pad-zeroed, V plain ----
__global__ void cvt_kernel(const float* __restrict__ q, const float* __restrict__ k,
                           const float* __restrict__ v, const int* __restrict__ pad)
{
    const size_t T = (size_t)BATCH * 2048 * 128 / 4;
    for (size_t i = (size_t)blockIdx.x * blockDim.x + threadIdx.x;
         i < 3 * T; i += (size_t)gridDim.x * blockDim.x) {
        if (i < T) {
            float4 x = reinterpret_cast<const float4*>(q)[i];
            uint2 h;
            h.x = packh2(x.x * SCALE_LOG2E, x.y * SCALE_LOG2E);
            h.y = packh2(x.z * SCALE_LOG2E, x.w * SCALE_LOG2E);
            *reinterpret_cast<uint2*>(g_Qh + i * 4) = h;
        } else if (i < 2 * T) {
            size_t f = i - T;
            size_t row = f >> 5;
            int b = (int)(row >> 11), m = (int)(row & 2047);
            uint2 h;
            if (m >= MK - pad[b]) {
                h.x = 0u; h.y = 0u;
            } else {
                float4 x = reinterpret_cast<const float4*>(k)[f];
                h.x = packh2(x.x, x.y);
                h.y = packh2(x.z, x.w);
            }
            *reinterpret_cast<uint2*>(g_Kh + f * 4) = h;
        } else {
            size_t f = i - 2 * T;
            float4 x = reinterpret_cast<const float4*>(v)[f];
            uint2 h;
            h.x = packh2(x.x, x.y);
            h.y = packh2(x.z, x.w);
            *reinterpret_cast<uint2*>(g_Vh + f * 4) = h;
        }
    }
}

// ---- main kernel: BM=64, 4 warps, 2 CTAs/SM, ring-3, fused soft+PV ----
__global__ __launch_bounds__(NTC, 2)
void fa_f16f_kernel(const int* __restrict__ pad, float* __restrict__ out)
{
    extern __shared__ __half sm[];
    const uint32_t S = sptr(sm);
    const int tid = threadIdx.x, lane = tid & 31, warp = tid >> 5;
    const int b = blockIdx.x & 15, tile = (NQ / BM - 1) - (blockIdx.x >> 4);
    const int nkb = tile + 1;

    const __half* qsrc  = g_Qh + ((size_t)b * NQ + (size_t)tile * BM) * DH;
    const __half* kbase = g_Kh + (size_t)b * MK * DH;
    const __half* vbase = g_Vh + (size_t)b * MK * DV;

    // prologue: group0 = Q + K0 + V0; group1 = K1 + V1
    stage64(S, SM_Q, qsrc, tid);
    stage64(S, SM_K(0), kbase, tid);
    stage64(S, SM_V(0), vbase, tid);
    cpc();
    if (nkb > 1) {
        stage64(S, SM_K(1), kbase + (size_t)BN * DH, tid);
        stage64(S, SM_V(1), vbase + (size_t)BN * DV, tid);
        cpc();
        cpw1();                 // Q + K0/V0 resident
    } else {
        cpw0();
    }
    __syncthreads();

    // persistent Q fragments (warp rows 16w..16w+16)
    const int r0w = warp * 16;
    uint32_t qf[8][4];
    {
        int qrow = r0w + (lane & 15);
        int dsel = (lane >> 4) << 3;
        #pragma unroll
        for (int kc = 0; kc < 8; ++kc)
            ldsm_x4(S + SM_Q + 2 * swz(qrow, kc * 16 + dsel),
                    qf[kc][0], qf[kc][1], qf[kc][2], qf[kc][3]);
    }

    const int rA = tile * BM + r0w + (lane >> 2);
    const int rB = rA + 8;
    float lA = 0.f, lB = 0.f;
    float oacc[16][4];
    #pragma unroll
    for (int t = 0; t < 16; ++t) {
        oacc[t][0] = 0.f; oacc[t][1] = 0.f; oacc[t][2] = 0.f; oacc[t][3] = 0.f;
    }

    for (int kb = 0; kb < nkb; ++kb) {
        const int cur = kb % 3;
        float sacc[8][4];

        // stage kb+2 into the slot read during iter kb-1 (freed by last sync)
        if (kb + 2 < nkb) {
            const int nxt2 = (kb + 2) % 3;
            stage64(S, SM_K(nxt2), kbase + (size_t)(kb + 2) * BN * DH, tid);
            stage64(S, SM_V(nxt2), vbase + (size_t)(kb + 2) * BN * DV, tid);
            cpc();
        }

        qk_block(sacc, S + SM_K(cur), qf, lane);

        // fused soft+PV at kt granularity — MUFU hides under HMMA drain
        const bool diag = (kb == tile);
        const int kbBase = kb * BN;
        const uint32_t vbuf = S + SM_V(cur);
        #pragma unroll
        for (int kt = 0; kt < 4; ++kt)
            soft_pv_kt(sacc, oacc, vbuf, kt, diag, kbBase, rA, rB, lane, lA, lB);

        if (kb + 1 < nkb) {
            if (kb + 2 < nkb) cpw1(); else cpw0();   // K/V[kb+1] resident
            __syncthreads();                          // single barrier per iter
        }
    }

    // epilogue
    lA += __shfl_xor_sync(0xffffffffu, lA, 1);
    lA += __shfl_xor_sync(0xffffffffu, lA, 2);
    lB += __shfl_xor_sync(0xffffffffu, lB, 1);
    lB += __shfl_xor_sync(0xffffffffu, lB, 2);
    const float invA = 1.0f / lA;
    const float invB = 1.0f / lB;

    float* obase = out + (size_t)b * NQ * DV;
    #pragma unroll
    for (int t = 0; t < 16; ++t) {
        int col = t * 8 + 2 * (lane & 3);
        float2 va = make_float2(oacc[t][0] * invA, oacc[t][1] * invA);
        float2 vb = make_float2(oacc[t][2] * invB, oacc[t][3] * invB);
        *(float2*)(obase + (size_t)rA * DV + col) = va;
        *(float2*)(obase + (size_t)rB * DV + col) = vb;
    }
}

extern "C" void kernel_launch(void* const* d_in, const int* in_sizes, int n_in,
                              void* d_out, int out_size)
{
    const float* q   = (const float*)d_in[0];
    const float* k   = (const float*)d_in[1];
    const float* v   = (const float*)d_in[2];
    const int*   pad = (const int*)d_in[3];
    float* out = (float*)d_out;

    cvt_kernel<<<2048, 256>>>(q, k, v, pad);

    cudaFuncSetAttribute(fa_f16f_kernel,
                         cudaFuncAttributeMaxDynamicSharedMemorySize, SM_TOTAL);
    fa_f16f_kernel<<<(NQ / BM) * BATCH, NTC, SM_TOTAL>>>(pad, out);
}

// round 16
// speedup vs baseline: 1.1973x; 1.1306x over previous
#include <cuda_runtime.h>
#include <cuda_fp16.h>
#include <stdint.h>

#define BATCH 16
#define NQ 2048
#define MK 2048
#define DH 128
#define DV 128
#define BM 64
#define BN 64
#define NTC 128
#define SCALE_LOG2E 0.1275174556684344f   // (1/sqrt(128)) * log2(e)

// fp16 pre-converted K/V, [b][m][d]. K rows with m >= keylen[b] are zeroed
// (exactly reproduces reference masking). Q is converted in-kernel.
__device__ __half g_Kh[(size_t)BATCH * MK * DH];
__device__ __half g_Vh[(size_t)BATCH * MK * DV];

// smem: Q 16KB + K ring3 48KB + V ring3 48KB = 112KB/CTA (2 CTAs/SM)
#define SM_Q 0
#define SM_K(i) (16384 + (i) * 16384)
#define SM_V(i) (65536 + (i) * 16384)
#define SM_TOTAL 114688

__device__ __forceinline__ int swz(int row, int d) {      // rows of 128 fp16
    return row * 128 + ((((d >> 3) ^ (row & 7)) << 3) | (d & 7));
}
__device__ __forceinline__ uint32_t sptr(const void* p) {
    return (uint32_t)__cvta_generic_to_shared(p);
}
__device__ __forceinline__ void cp16(uint32_t d, const void* s) {
    asm volatile("cp.async.cg.shared.global [%0], [%1], 16;" :: "r"(d), "l"(s));
}
__device__ __forceinline__ void cpc()  { asm volatile("cp.async.commit_group;"); }
__device__ __forceinline__ void cpw0() { asm volatile("cp.async.wait_group 0;"); }
__device__ __forceinline__ void cpw1() { asm volatile("cp.async.wait_group 1;"); }

__device__ __forceinline__ void ldsm_x4(uint32_t a, uint32_t& r0, uint32_t& r1,
                                        uint32_t& r2, uint32_t& r3) {
    asm volatile("ldmatrix.sync.aligned.m8n8.x4.shared.b16 {%0,%1,%2,%3}, [%4];"
                 : "=r"(r0), "=r"(r1), "=r"(r2), "=r"(r3) : "r"(a));
}
__device__ __forceinline__ void ldsm_x4_t(uint32_t a, uint32_t& r0, uint32_t& r1,
                                          uint32_t& r2, uint32_t& r3) {
    asm volatile("ldmatrix.sync.aligned.m8n8.x4.trans.shared.b16 {%0,%1,%2,%3}, [%4];"
                 : "=r"(r0), "=r"(r1), "=r"(r2), "=r"(r3) : "r"(a));
}
__device__ __forceinline__ void mma_f16(float* c, const uint32_t* a,
                                        uint32_t b0, uint32_t b1) {
    asm volatile(
        "mma.sync.aligned.m16n8k16.row.col.f32.f16.f16.f32 "
        "{%0,%1,%2,%3}, {%4,%5,%6,%7}, {%8,%9}, {%0,%1,%2,%3};"
        : "+f"(c[0]), "+f"(c[1]), "+f"(c[2]), "+f"(c[3])
        : "r"(a[0]), "r"(a[1]), "r"(a[2]), "r"(a[3]), "r"(b0), "r"(b1));
}
__device__ __forceinline__ uint32_t packh2(float x, float y) {
    __half2 h = __floats2half2_rn(x, y);
    return *reinterpret_cast<uint32_t*>(&h);
}
__device__ __forceinline__ uint32_t ex2h2(uint32_t x) {
    uint32_t r;
    asm("ex2.approx.f16x2 %0, %1;" : "=r"(r) : "r"(x));
    return r;
}
__device__ __forceinline__ uint32_t hadd2u(uint32_t a, uint32_t b) {
    __half2 r = __hadd2(*reinterpret_cast<__half2*>(&a),
                        *reinterpret_cast<__half2*>(&b));
    return *reinterpret_cast<uint32_t*>(&r);
}

__device__ __forceinline__ void stage64(uint32_t S, int off, const __half* src, int tid) {
    #pragma unroll
    for (int i = 0; i < 8; ++i) {
        int c = tid + i * NTC;             // 0..1023
        int row = c >> 4, ch = c & 15;
        cp16(S + off + 2 * (row * 128 + ((ch ^ (row & 7)) << 3)),
             src + (size_t)row * 128 + ch * 8);
    }
}

__device__ __forceinline__ void qk_block(float (&sacc)[8][4], uint32_t kbuf,
                                         const uint32_t (&qf)[8][4], int lane) {
    #pragma unroll
    for (int nt = 0; nt < 8; ++nt) {
        sacc[nt][0] = 0.f; sacc[nt][1] = 0.f; sacc[nt][2] = 0.f; sacc[nt][3] = 0.f;
    }
    const int key = lane & 7;
    const int dbase = (lane >> 3) << 3;
    #pragma unroll
    for (int nt = 0; nt < 8; ++nt) {
        int krow = nt * 8 + key;
        #pragma unroll
        for (int kc2 = 0; kc2 < 4; ++kc2) {
            int d = kc2 * 32 + dbase;
            uint32_t k0, k1, k2, k3;
            ldsm_x4(kbuf + 2 * swz(krow, d), k0, k1, k2, k3);
            mma_f16(sacc[nt], qf[2 * kc2],     k0, k1);
            mma_f16(sacc[nt], qf[2 * kc2 + 1], k2, k3);
        }
    }
}

// fp16x2 softmax: p = ex2(s_log2) in half2 pairs; masked -> -inf -> 0.
// l summed via depth-3 HADD2 tree, converted to f32 once per block.
__device__ __forceinline__ void soft_block(const float (&sacc)[8][4],
                                           uint32_t (&ph)[8][2],
                                           int kb, int tile, int rA, int rB,
                                           int lane, float& lA, float& lB) {
    if (kb == tile) {
        const int kbBase = kb * BN;
        #pragma unroll
        for (int nt = 0; nt < 8; ++nt) {
            int c0 = kbBase + nt * 8 + 2 * (lane & 3);
            float a0 = (c0     > rA) ? -1e30f : sacc[nt][0];
            float a1 = (c0 + 1 > rA) ? -1e30f : sacc[nt][1];
            float b0 = (c0     > rB) ? -1e30f : sacc[nt][2];
            float b1 = (c0 + 1 > rB) ? -1e30f : sacc[nt][3];
            ph[nt][0] = ex2h2(packh2(a0, a1));
            ph[nt][1] = ex2h2(packh2(b0, b1));
        }
    } else {
        #pragma unroll
        for (int nt = 0; nt < 8; ++nt) {
            ph[nt][0] = ex2h2(packh2(sacc[nt][0], sacc[nt][1]));
            ph[nt][1] = ex2h2(packh2(sacc[nt][2], sacc[nt][3]));
        }
    }
    uint32_t sA = hadd2u(hadd2u(hadd2u(ph[0][0], ph[1][0]), hadd2u(ph[2][0], ph[3][0])),
                         hadd2u(hadd2u(ph[4][0], ph[5][0]), hadd2u(ph[6][0], ph[7][0])));
    uint32_t sB = hadd2u(hadd2u(hadd2u(ph[0][1], ph[1][1]), hadd2u(ph[2][1], ph[3][1])),
                         hadd2u(hadd2u(ph[4][1], ph[5][1]), hadd2u(ph[6][1], ph[7][1])));
    float2 fa = __half22float2(*reinterpret_cast<__half2*>(&sA));
    float2 fb = __half22float2(*reinterpret_cast<__half2*>(&sB));
    lA += fa.x + fa.y;
    lB += fb.x + fb.y;
}

__device__ __forceinline__ void pv_block(float (&oacc)[16][4],
                                         const uint32_t (&ph)[8][2],
                                         uint32_t vbuf, int lane) {
    const int vkey = lane & 15;
    const int nsel = (lane >> 4) << 3;
    #pragma unroll
    for (int kt = 0; kt < 4; ++kt) {
        uint32_t pa[4];
        pa[0] = ph[2 * kt][0];
        pa[1] = ph[2 * kt][1];
        pa[2] = ph[2 * kt + 1][0];
        pa[3] = ph[2 * kt + 1][1];
        int krow = kt * 16 + vkey;
        #pragma unroll
        for (int nt2 = 0; nt2 < 8; ++nt2) {
            int n0 = nt2 * 16 + nsel;
            uint32_t v0, v1, v2, v3;
            ldsm_x4_t(vbuf + 2 * swz(krow, n0), v0, v1, v2, v3);
            mma_f16(oacc[2 * nt2],     pa, v0, v1);
            mma_f16(oacc[2 * nt2 + 1], pa, v2, v3);
        }
    }
}

// ---- pre-pass: K pad-zeroed, V plain (Q handled in main kernel) ----
__global__ void cvt_kernel(const float* __restrict__ k, const float* __restrict__ v,
                           const int* __restrict__ pad)
{
    const size_t T = (size_t)BATCH * 2048 * 128 / 4;
    for (size_t i = (size_t)blockIdx.x * blockDim.x + threadIdx.x;
         i < 2 * T; i += (size_t)gridDim.x * blockDim.x) {
        if (i < T) {
            size_t f = i;
            size_t row = f >> 5;
            int b = (int)(row >> 11), m = (int)(row & 2047);
            uint2 h;
            if (m >= MK - pad[b]) {
                h.x = 0u; h.y = 0u;
            } else {
                float4 x = reinterpret_cast<const float4*>(k)[f];
                h.x = packh2(x.x, x.y);
                h.y = packh2(x.z, x.w);
            }
            *reinterpret_cast<uint2*>(g_Kh + f * 4) = h;
        } else {
            size_t f = i - T;
            float4 x = reinterpret_cast<const float4*>(v)[f];
            uint2 h;
            h.x = packh2(x.x, x.y);
            h.y = packh2(x.z, x.w);
            *reinterpret_cast<uint2*>(g_Vh + f * 4) = h;
        }
    }
}

// ---- main kernel: BM=64, 4 warps, 2 CTAs/SM, ring-3, f16x2 exp ----
__global__ __launch_bounds__(NTC, 2)
void fa_f16g_kernel(const float* __restrict__ q, float* __restrict__ out)
{
    extern __shared__ __half sm[];
    const uint32_t S = sptr(sm);
    const int tid = threadIdx.x, lane = tid & 31, warp = tid >> 5;
    const int b = blockIdx.x & 15, tile = (NQ / BM - 1) - (blockIdx.x >> 4);
    const int nkb = tile + 1;

    const __half* kbase = g_Kh + (size_t)b * MK * DH;
    const __half* vbase = g_Vh + (size_t)b * MK * DV;

    // prologue: stage K0/V0 (group0), K1/V1 (group1); convert Q in-kernel
    stage64(S, SM_K(0), kbase, tid);
    stage64(S, SM_V(0), vbase, tid);
    cpc();
    if (nkb > 1) {
        stage64(S, SM_K(1), kbase + (size_t)BN * DH, tid);
        stage64(S, SM_V(1), vbase + (size_t)BN * DV, tid);
        cpc();
    }

    // Q: fp32 -> fp16 (scaled to log2 domain), swizzled STS
    {
        const float* qf32 = q + ((size_t)b * NQ + (size_t)tile * BM) * DH;
        #pragma unroll
        for (int i = 0; i < 16; ++i) {
            int c = tid + i * NTC;         // float4 idx 0..2047
            int row = c >> 5, c4 = c & 31; // 32 float4 per row
            float4 x = *reinterpret_cast<const float4*>(qf32 + (size_t)row * DH + c4 * 4);
            uint2 h;
            h.x = packh2(x.x * SCALE_LOG2E, x.y * SCALE_LOG2E);
            h.y = packh2(x.z * SCALE_LOG2E, x.w * SCALE_LOG2E);
            *reinterpret_cast<uint2*>(reinterpret_cast<char*>(sm) +
                                      2 * swz(row, c4 * 4)) = h;
        }
    }
    if (nkb > 1) cpw1(); else cpw0();      // K0/V0 resident
    __syncthreads();                       // Q STS visible to all warps

    // persistent Q fragments (warp rows 16w..16w+16)
    const int r0w = warp * 16;
    uint32_t qf[8][4];
    {
        int qrow = r0w + (lane & 15);
        int dsel = (lane >> 4) << 3;
        #pragma unroll
        for (int kc = 0; kc < 8; ++kc)
            ldsm_x4(S + SM_Q + 2 * swz(qrow, kc * 16 + dsel),
                    qf[kc][0], qf[kc][1], qf[kc][2], qf[kc][3]);
    }

    const int rA = tile * BM + r0w + (lane >> 2);
    const int rB = rA + 8;
    float lA = 0.f, lB = 0.f;
    float oacc[16][4];
    #pragma unroll
    for (int t = 0; t < 16; ++t) {
        oacc[t][0] = 0.f; oacc[t][1] = 0.f; oacc[t][2] = 0.f; oacc[t][3] = 0.f;
    }

    for (int kb = 0; kb < nkb; ++kb) {
        const int cur = kb % 3;
        float sacc[8][4];
        uint32_t ph[8][2];

        // stage kb+2 into the slot read during iter kb-1 (freed by last sync)
        if (kb + 2 < nkb) {
            const int nxt2 = (kb + 2) % 3;
            stage64(S, SM_K(nxt2), kbase + (size_t)(kb + 2) * BN * DH, tid);
            stage64(S, SM_V(nxt2), vbase + (size_t)(kb + 2) * BN * DV, tid);
            cpc();
        }

        qk_block(sacc, S + SM_K(cur), qf, lane);
        soft_block(sacc, ph, kb, tile, rA, rB, lane, lA, lB);
        pv_block(oacc, ph, S + SM_V(cur), lane);

        if (kb + 1 < nkb) {
            if (kb + 2 < nkb) cpw1(); else cpw0();   // K/V[kb+1] resident
            __syncthreads();                          // single barrier per iter
        }
    }

    // epilogue
    lA += __shfl_xor_sync(0xffffffffu, lA, 1);
    lA += __shfl_xor_sync(0xffffffffu, lA, 2);
    lB += __shfl_xor_sync(0xffffffffu, lB, 1);
    lB += __shfl_xor_sync(0xffffffffu, lB, 2);
    const float invA = 1.0f / lA;
    const float invB = 1.0f / lB;

    float* obase = out + (size_t)b * NQ * DV;
    #pragma unroll
    for (int t = 0; t < 16; ++t) {
        int col = t * 8 + 2 * (lane & 3);
        float2 va = make_float2(oacc[t][0] * invA, oacc[t][1] * invA);
        float2 vb = make_float2(oacc[t][2] * invB, oacc[t][3] * invB);
        *(float2*)(obase + (size_t)rA * DV + col) = va;
        *(float2*)(obase + (size_t)rB * DV + col) = vb;
    }
}

extern "C" void kernel_launch(void* const* d_in, const int* in_sizes, int n_in,
                              void* d_out, int out_size)
{
    const float* q   = (const float*)d_in[0];
    const float* k   = (const float*)d_in[1];
    const float* v   = (const float*)d_in[2];
    const int*   pad = (const int*)d_in[3];
    float* out = (float*)d_out;

    cvt_kernel<<<2048, 256>>>(k, v, pad);

    cudaFuncSetAttribute(fa_f16g_kernel,
                         cudaFuncAttributeMaxDynamicSharedMemorySize, SM_TOTAL);
    fa_f16g_kernel<<<(NQ / BM) * BATCH, NTC, SM_TOTAL>>>(q, out);
}